// round 15
// baseline (speedup 1.0000x reference)
#include <cuda_runtime.h>
#include <cuda_fp16.h>

typedef unsigned int u32;

#define HIDDEN 256
#define INDIM  72
#define MT     64
#define NT     512
#define RS     48                 // bytes per 16-half activation row (+16B pad)
#define KSB    (MT*RS)            // 3072 bytes per ks-region
#define UAB    (21*KSB)           // 64512 bytes per activation buffer
#define CSS    72                 // c-state stride (floats) per unit, padded
#define SMEM_BYTES (2*UAB + 256*CSS*4)   // 202752

// ---------------- packed weight fragment arrays ----------------
// gates B-frags: [ntg 0..127][pp 0..11][lane] x 8 halfs (uint4)
//   ntg = 2*T + s ; T = pair-column tile (8 cols), s=0:(i,f), s=1:(g,o)
//   pp 0..7 : h-part ks pairs (5+2p, 6+2p); pp8: ks4 h-half (x zeroed)
//   pp 9,10 : x-part ks pairs (0,1),(2,3);  pp11: ks4 x-half (h zeroed)
__device__ __align__(16) __half g_wb[128 * 12 * 32 * 8];
__device__ __align__(16) float  g_bf[128 * 32 * 2];     // gate bias C-frags
__device__ __align__(16) __half g_wi[64 * 16 * 32 * 4]; // init (h,c)-interleaved
__device__ __align__(16) float  g_bi[64 * 32 * 2];      // init bias C-frags
__device__ __align__(16) __half g_wy[9 * 17 * 32 * 4];  // y frags, ky0=ks4 (x zeroed)

__device__ __forceinline__ void ldm4(u32 r[4], u32 a) {
    asm volatile("ldmatrix.sync.aligned.m8n8.x4.shared.b16 {%0,%1,%2,%3},[%4];"
                 : "=r"(r[0]), "=r"(r[1]), "=r"(r[2]), "=r"(r[3]) : "r"(a));
}
__device__ __forceinline__ void hmma(float C[4], const u32 A[4], u32 b0, u32 b1) {
    asm("mma.sync.aligned.m16n8k16.row.col.f32.f16.f16.f32 "
        "{%0,%1,%2,%3},{%4,%5,%6,%7},{%8,%9},{%0,%1,%2,%3};"
        : "+f"(C[0]), "+f"(C[1]), "+f"(C[2]), "+f"(C[3])
        : "r"(A[0]), "r"(A[1]), "r"(A[2]), "r"(A[3]), "r"(b0), "r"(b1));
}
__device__ __forceinline__ float tanha(float x) {
    float r; asm("tanh.approx.f32 %0,%1;" : "=f"(r) : "f"(x)); return r;
}
__device__ __forceinline__ float siga(float x) {
    return fmaf(0.5f, tanha(0.5f * x), 0.5f);
}

// ---------------- prep ----------------
__global__ void prep_kernel(const float* __restrict__ W_ih, const float* __restrict__ W_hh,
                            const float* __restrict__ b_ih, const float* __restrict__ b_hh,
                            const float* __restrict__ Wh,   const float* __restrict__ Wc,
                            const float* __restrict__ Wo,   const float* __restrict__ bh,
                            const float* __restrict__ bc) {
    const int tid = blockIdx.x * blockDim.x + threadIdx.x;
    const int stride = gridDim.x * blockDim.x;

    // gates B frags (ntg = 2T + s)
    for (int i = tid; i < 128 * 12 * 32 * 8; i += stride) {
        int e = i & 7, lane = (i >> 3) & 31, r = i >> 8;
        int pp = r % 12, ntg = r / 12;
        int T = ntg >> 1, s = ntg & 1;
        int gid = lane >> 2, tig = lane & 3;
        int col = 8 * T + gid;
        int u = col >> 1, comp = col & 1;
        int g = s ? (comp ? 3 : 2) : (comp ? 1 : 0);   // i,f,g,o torch order
        int n = g * 256 + u;
        int khalf = 2 * tig + (e & 1) + 8 * ((e >> 1) & 1);
        float v = 0.0f;
        int ks = -1, mode = 0;
        if (pp < 8)       { ks = 5 + 2 * pp + (e >> 2); }
        else if (pp == 8) { if (e < 4) { ks = 4; mode = 1; } }
        else if (pp < 11) { ks = 2 * (pp - 9) + (e >> 2); }
        else              { if (e < 4) { ks = 4; mode = 2; } }
        if (ks >= 0) {
            int k = ks * 16 + khalf;
            if (k < 328) {
                bool isx = (k < INDIM);
                if (!((mode == 1 && isx) || (mode == 2 && !isx)))
                    v = isx ? W_ih[n * INDIM + k] : W_hh[n * HIDDEN + (k - INDIM)];
            }
        }
        g_wb[i] = __float2half(v);
    }
    // gates bias frags
    for (int i = tid; i < 128 * 64; i += stride) {
        int e = i & 1, lane = (i >> 1) & 31, ntg = i >> 6;
        int T = ntg >> 1, s = ntg & 1;
        int tig = lane & 3;
        int col = 8 * T + 2 * tig + e;
        int u = col >> 1, comp = col & 1;
        int g = s ? (comp ? 3 : 2) : (comp ? 1 : 0);
        int n = g * 256 + u;
        g_bf[i] = b_ih[n] + b_hh[n];
    }
    // init B frags: (h,c) interleaved columns
    for (int i = tid; i < 64 * 16 * 32 * 4; i += stride) {
        int e = i & 3, lane = (i >> 2) & 31, r = i >> 7;
        int ks = r & 15, T = r >> 4;
        int gid = lane >> 2, tig = lane & 3;
        int col = 8 * T + gid;
        int u = col >> 1, comp = col & 1;
        int k = ks * 16 + 2 * tig + (e & 1) + 8 * (e >> 1);
        float v = comp ? Wc[u * HIDDEN + k] : Wh[u * HIDDEN + k];
        g_wi[i] = __float2half(v);
    }
    // init bias frags
    for (int i = tid; i < 64 * 64; i += stride) {
        int e = i & 1, lane = (i >> 1) & 31, T = i >> 6;
        int tig = lane & 3;
        int col = 8 * T + 2 * tig + e;
        int u = col >> 1, comp = col & 1;
        g_bi[i] = comp ? bc[u] : bh[u];
    }
    // y B frags
    for (int i = tid; i < 9 * 17 * 32 * 4; i += stride) {
        int e = i & 3, lane = (i >> 2) & 31, r = i >> 7;
        int ky = r % 17, nt = r / 17;
        int gid = lane >> 2, tig = lane & 3;
        int k = (ky + 4) * 16 + 2 * tig + (e & 1) + 8 * (e >> 1);
        int kw = k - INDIM;
        int n = nt * 8 + gid;
        float v = (kw >= 0 && kw < HIDDEN) ? Wo[n * HIDDEN + kw] : 0.0f;
        g_wy[i] = __float2half(v);
    }
}

// ---------------- gates pass helpers ----------------
__device__ __forceinline__ void gates_hpart(float C[4][4][4], float Y[4][4], bool doy,
                                            u32 R, u32 aoff, const uint4* wsl,
                                            const uint2* wyp) {
    u32 A[4][4];
#pragma unroll
    for (int mi = 0; mi < 4; mi++) ldm4(A[mi], R + 4 * KSB + mi * 16 * RS + aoff);
#pragma unroll
    for (int q = 0; q < 4; q++) {
        uint4 wf = wsl[(q * 12 + 8) * 32];
#pragma unroll
        for (int mi = 0; mi < 4; mi++) hmma(C[mi][q], A[mi], wf.x, wf.y);
    }
    if (doy) {
        uint2 wy = wyp[0];
#pragma unroll
        for (int mi = 0; mi < 4; mi++) hmma(Y[mi], A[mi], wy.x, wy.y);
    }
#pragma unroll
    for (int p = 0; p < 8; p++) {
        const int ksa = 5 + 2 * p;
        uint4 wf[4];
#pragma unroll
        for (int q = 0; q < 4; q++) wf[q] = wsl[(q * 12 + p) * 32];
#pragma unroll
        for (int mi = 0; mi < 4; mi++) ldm4(A[mi], R + ksa * KSB + mi * 16 * RS + aoff);
#pragma unroll
        for (int q = 0; q < 4; q++)
#pragma unroll
            for (int mi = 0; mi < 4; mi++) hmma(C[mi][q], A[mi], wf[q].x, wf[q].y);
        if (doy) {
            uint2 wy = wyp[(ksa - 4) * 32];
#pragma unroll
            for (int mi = 0; mi < 4; mi++) hmma(Y[mi], A[mi], wy.x, wy.y);
        }
#pragma unroll
        for (int mi = 0; mi < 4; mi++) ldm4(A[mi], R + (ksa + 1) * KSB + mi * 16 * RS + aoff);
#pragma unroll
        for (int q = 0; q < 4; q++)
#pragma unroll
            for (int mi = 0; mi < 4; mi++) hmma(C[mi][q], A[mi], wf[q].z, wf[q].w);
        if (doy) {
            uint2 wy = wyp[(ksa - 3) * 32];
#pragma unroll
            for (int mi = 0; mi < 4; mi++) hmma(Y[mi], A[mi], wy.x, wy.y);
        }
    }
}

__device__ __forceinline__ void gates_xpart(float C[4][4][4], u32 R, u32 aoff,
                                            const uint4* wsl) {
    u32 A[4][4];
#pragma unroll
    for (int pb = 0; pb < 2; pb++) {
        const int ks0 = 2 * pb;
        uint4 wf[4];
#pragma unroll
        for (int q = 0; q < 4; q++) wf[q] = wsl[(q * 12 + 9 + pb) * 32];
#pragma unroll
        for (int mi = 0; mi < 4; mi++) ldm4(A[mi], R + ks0 * KSB + mi * 16 * RS + aoff);
#pragma unroll
        for (int q = 0; q < 4; q++)
#pragma unroll
            for (int mi = 0; mi < 4; mi++) hmma(C[mi][q], A[mi], wf[q].x, wf[q].y);
#pragma unroll
        for (int mi = 0; mi < 4; mi++) ldm4(A[mi], R + (ks0 + 1) * KSB + mi * 16 * RS + aoff);
#pragma unroll
        for (int q = 0; q < 4; q++)
#pragma unroll
            for (int mi = 0; mi < 4; mi++) hmma(C[mi][q], A[mi], wf[q].z, wf[q].w);
    }
#pragma unroll
    for (int mi = 0; mi < 4; mi++) ldm4(A[mi], R + 4 * KSB + mi * 16 * RS + aoff);
#pragma unroll
    for (int q = 0; q < 4; q++) {
        uint4 wf = wsl[(q * 12 + 11) * 32];
#pragma unroll
        for (int mi = 0; mi < 4; mi++) hmma(C[mi][q], A[mi], wf.x, wf.y);
    }
}

// ---------------- fused LSTM main ----------------
__global__ void __launch_bounds__(NT, 1)
lstm_main(const float* __restrict__ z, const float* __restrict__ bo,
          float* __restrict__ out) {
    extern __shared__ __align__(16) char sm[];
    u32* smw = (u32*)sm;
    const u32 base = (u32)__cvta_generic_to_shared(sm);
    float* csf = (float*)(sm + 2 * UAB);

    const int tid  = threadIdx.x;
    const int m0   = blockIdx.x * MT;
    const int lane = tid & 31;
    const int w    = tid >> 5;
    const int gid  = lane >> 2;
    const int tig  = lane & 3;
    const int g8 = lane >> 3, ri = lane & 7;
    const u32 aoff = (u32)(((g8 & 1) * 8 + ri) * RS + (g8 >> 1) * 16);

    // ---- zero buf0; stage z into buf1 ----
    for (int i = tid; i < UAB / 4; i += NT) smw[i] = 0u;
    for (int ii = tid; ii < MT * 128; ii += NT) {
        int m = ii >> 7, k2 = ii & 127;
        float2 zv = *(const float2*)&z[(size_t)(m0 + m) * HIDDEN + 2 * k2];
        __half2 hv = __floats2half2_rn(zv.x, zv.y);
        smw[UAB / 4 + (k2 >> 3) * (KSB / 4) + m * (RS / 4) + (k2 & 7)] =
            *reinterpret_cast<u32*>(&hv);
    }
    __syncthreads();

    // ---- init GEMM: h -> buf0, c -> cs ----
    {
        float C[4][4][4];
#pragma unroll
        for (int jj = 0; jj < 4; jj++) {
            float2 bb = *(const float2*)&g_bi[((w * 4 + jj) * 32 + lane) * 2];
#pragma unroll
            for (int mi = 0; mi < 4; mi++) {
                C[mi][jj][0] = bb.x; C[mi][jj][1] = bb.y;
                C[mi][jj][2] = bb.x; C[mi][jj][3] = bb.y;
            }
        }
        const uint2* wip = (const uint2*)g_wi + (w * 4) * 16 * 32 + lane;
        const u32 za = base + UAB;
#pragma unroll
        for (int ks = 0; ks < 16; ks++) {
            u32 A[4][4];
#pragma unroll
            for (int mi = 0; mi < 4; mi++) ldm4(A[mi], za + ks * KSB + mi * 16 * RS + aoff);
#pragma unroll
            for (int jj = 0; jj < 4; jj++) {
                uint2 wf = wip[(jj * 16 + ks) * 32];
#pragma unroll
                for (int mi = 0; mi < 4; mi++) hmma(C[mi][jj], A[mi], wf.x, wf.y);
            }
        }
#pragma unroll
        for (int mi = 0; mi < 4; mi++)
#pragma unroll
            for (int jj = 0; jj < 4; jj++) {
                int u = 16 * w + 4 * jj + tig;
                int kt = INDIM + u;
                u32 hb = base + (kt >> 4) * KSB + (kt & 15) * 2;
                int r0 = 16 * mi + gid;
                unsigned short h0 = __half_as_ushort(__float2half_rn(C[mi][jj][0]));
                unsigned short h1 = __half_as_ushort(__float2half_rn(C[mi][jj][2]));
                asm volatile("st.shared.u16 [%0], %1;" :: "r"(hb + r0 * RS), "h"(h0));
                asm volatile("st.shared.u16 [%0], %1;" :: "r"(hb + (r0 + 8) * RS), "h"(h1));
                csf[u * CSS + r0]     = C[mi][jj][1];
                csf[u * CSS + r0 + 8] = C[mi][jj][3];
            }
    }
    __syncthreads();

    const float2* bf2 = (const float2*)g_bf;
    const uint2*  wyp = (const uint2*)g_wy + (w * 17) * 32 + lane;   // valid for w<9
    float2 ybb = make_float2(0.f, 0.f);
    if (w < 9) ybb = *(const float2*)&bo[w * 8 + 2 * tig];
    const int ycol = w * 8 + 2 * tig;

    for (int step = 0; step < 8; step++) {
        const u32 R  = base + (step & 1) * UAB;
        const u32 Wb = base + ((step + 1) & 1) * UAB;

#pragma unroll
        for (int P = 0; P < 2; P++) {
            float C[4][4][4];
            float Y[4][4];
            const bool doy = (P == 0) && (w < 9) && (step > 0);
#pragma unroll
            for (int q = 0; q < 4; q++) {
                float2 bb = bf2[(64 * P + 4 * w + q) * 32 + lane];
#pragma unroll
                for (int mi = 0; mi < 4; mi++) {
                    C[mi][q][0] = bb.x; C[mi][q][1] = bb.y;
                    C[mi][q][2] = bb.x; C[mi][q][3] = bb.y;
                }
            }
            if (doy) {
#pragma unroll
                for (int mi = 0; mi < 4; mi++) {
                    Y[mi][0] = ybb.x; Y[mi][1] = ybb.y;
                    Y[mi][2] = ybb.x; Y[mi][3] = ybb.y;
                }
            }
            const uint4* wsl = (const uint4*)g_wb + ((64 * P + 4 * w) * 12) * 32 + lane;

            gates_hpart(C, Y, doy, R, aoff, wsl, wyp);

            if (P == 0) {
                if (doy) {
                    // y(step-1) epilogue: out store + x feedback into R.x
                    u32 xaddr = R + (ycol >> 4) * KSB + (ycol & 15) * 2;
#pragma unroll
                    for (int mi = 0; mi < 4; mi++) {
                        float y0 = siga(Y[mi][0]), y1 = siga(Y[mi][1]);
                        float y2 = siga(Y[mi][2]), y3 = siga(Y[mi][3]);
                        int r0 = 16 * mi + gid;
                        size_t ob0 = ((size_t)(m0 + r0) * 8 + (step - 1)) * INDIM + ycol;
                        size_t ob1 = ((size_t)(m0 + r0 + 8) * 8 + (step - 1)) * INDIM + ycol;
                        *(float2*)&out[ob0] = make_float2(y0, y1);
                        *(float2*)&out[ob1] = make_float2(y2, y3);
                        __half2 xa = __floats2half2_rn(y0, y1);
                        __half2 xb = __floats2half2_rn(y2, y3);
                        asm volatile("st.shared.u32 [%0], %1;"
                                     :: "r"(xaddr + r0 * RS), "r"(*reinterpret_cast<u32*>(&xa)));
                        asm volatile("st.shared.u32 [%0], %1;"
                                     :: "r"(xaddr + (r0 + 8) * RS), "r"(*reinterpret_cast<u32*>(&xb)));
                    }
                }
                __syncthreads();   // x(step) ready in R.x
            }

            gates_xpart(C, R, aoff, wsl);

            // ---- elementwise: c in SMEM, h -> write buffer ----
#pragma unroll
            for (int jj = 0; jj < 2; jj++) {
                int u = 128 * P + 8 * w + 4 * jj + tig;
                int kt = INDIM + u;
                u32 hb = Wb + (kt >> 4) * KSB + (kt & 15) * 2;
#pragma unroll
                for (int mi = 0; mi < 4; mi++) {
#pragma unroll
                    for (int rr = 0; rr < 2; rr++) {
                        int row = 16 * mi + gid + 8 * rr;
                        float iv = siga(C[mi][2 * jj][2 * rr]);
                        float fv = siga(C[mi][2 * jj][2 * rr + 1]);
                        float gv = tanha(C[mi][2 * jj + 1][2 * rr]);
                        float ov = siga(C[mi][2 * jj + 1][2 * rr + 1]);
                        float cc = fmaf(fv, csf[u * CSS + row], iv * gv);
                        csf[u * CSS + row] = cc;
                        float h = ov * tanha(cc);
                        unsigned short hr = __half_as_ushort(__float2half_rn(h));
                        asm volatile("st.shared.u16 [%0], %1;"
                                     :: "r"(hb + row * RS), "h"(hr));
                    }
                }
            }
        }
        __syncthreads();   // write buffer complete before next step
    }

    // ---- final y(7) from buf0 ----
    if (w < 9) {
        const u32 R = base;   // step 8 read buffer = buf0 (holds h(8th))
        float Y[4][4];
#pragma unroll
        for (int mi = 0; mi < 4; mi++) {
            Y[mi][0] = ybb.x; Y[mi][1] = ybb.y;
            Y[mi][2] = ybb.x; Y[mi][3] = ybb.y;
        }
#pragma unroll
        for (int ky = 0; ky < 17; ky++) {
            int ks = ky + 4;
            u32 A[4][4];
#pragma unroll
            for (int mi = 0; mi < 4; mi++) ldm4(A[mi], R + ks * KSB + mi * 16 * RS + aoff);
            uint2 wy = wyp[ky * 32];
#pragma unroll
            for (int mi = 0; mi < 4; mi++) hmma(Y[mi], A[mi], wy.x, wy.y);
        }
#pragma unroll
        for (int mi = 0; mi < 4; mi++) {
            float y0 = siga(Y[mi][0]), y1 = siga(Y[mi][1]);
            float y2 = siga(Y[mi][2]), y3 = siga(Y[mi][3]);
            int r0 = 16 * mi + gid;
            size_t ob0 = ((size_t)(m0 + r0) * 8 + 7) * INDIM + ycol;
            size_t ob1 = ((size_t)(m0 + r0 + 8) * 8 + 7) * INDIM + ycol;
            *(float2*)&out[ob0] = make_float2(y0, y1);
            *(float2*)&out[ob1] = make_float2(y2, y3);
        }
    }
}

extern "C" void kernel_launch(void* const* d_in, const int* in_sizes, int n_in,
                              void* d_out, int out_size) {
    const float* z    = (const float*)d_in[0];
    const float* W_ih = (const float*)d_in[1];
    const float* W_hh = (const float*)d_in[2];
    const float* b_ih = (const float*)d_in[3];
    const float* b_hh = (const float*)d_in[4];
    const float* Wh   = (const float*)d_in[5];
    const float* bh   = (const float*)d_in[6];
    const float* Wc   = (const float*)d_in[7];
    const float* bc   = (const float*)d_in[8];
    const float* Wo   = (const float*)d_in[9];
    const float* bo   = (const float*)d_in[10];
    float* out = (float*)d_out;

    int B = in_sizes[0] / HIDDEN;   // z is (1, B, 256)

    cudaFuncSetAttribute(lstm_main, cudaFuncAttributeMaxDynamicSharedMemorySize, SMEM_BYTES);
    prep_kernel<<<512, 256>>>(W_ih, W_hh, b_ih, b_hh, Wh, Wc, Wo, bh, bc);
    lstm_main<<<B / MT, NT, SMEM_BYTES>>>(z, bo, out);
}